// round 6
// baseline (speedup 1.0000x reference)
#include <cuda_runtime.h>
#include <cuda_bf16.h>
#include <cstdint>
#include <math.h>

#define B_   4
#define LQ_  2048
#define LK_  2048
#define IND  1024
#define NH_  16
#define HD_  64
#define HDA  1024
#define NZ   (B_*NH_)
#define NEGV (-1e9f)
#define STRD 40   // smem tile stride in halves (80B: 16B-aligned, ldmatrix conflict-free)

// ---------------- scratch (device globals) ----------------
__device__ __nv_bfloat16 g_Qhi[(size_t)NZ * LQ_ * HD_];   // [z][l][d]
__device__ __nv_bfloat16 g_Qlo[(size_t)NZ * LQ_ * HD_];
__device__ __nv_bfloat16 g_Khi[(size_t)NZ * LK_ * HD_];
__device__ __nv_bfloat16 g_Klo[(size_t)NZ * LK_ * HD_];
__device__ __nv_bfloat16 g_Vthi[(size_t)NZ * HD_ * LK_];  // [z][d][l]
__device__ __nv_bfloat16 g_Vtlo[(size_t)NZ * HD_ * LK_];
__device__ float  g_Vf[(size_t)NZ * LK_ * HD_];           // [z][l][d]
__device__ float  g_Oh[(size_t)B_ * LQ_ * HDA];           // [b][q][h*d]
__device__ float2 g_part[(size_t)NZ * 64 * LQ_];          // per-(z, 32col-tile, row)
__device__ float2 g_stats[(size_t)NZ * LQ_];              // {rowmax, 1/rowsum}

// ---------------- helpers ----------------
__device__ __forceinline__ uint32_t smem_u32(const void* p) {
    uint32_t a;
    asm("{ .reg .u64 t; cvta.to.shared.u64 t, %1; cvt.u32.u64 %0, t; }" : "=r"(a) : "l"(p));
    return a;
}

__device__ __forceinline__ void ldsm4(uint32_t (&r)[4], uint32_t addr) {
    asm volatile("ldmatrix.sync.aligned.m8n8.x4.shared.b16 {%0,%1,%2,%3}, [%4];"
                 : "=r"(r[0]), "=r"(r[1]), "=r"(r[2]), "=r"(r[3]) : "r"(addr));
}

// fragment address: tile row-major [rows][STRD] halves; m16xk16 (or n16xk16) at (row0,k0)
__device__ __forceinline__ uint32_t frag_addr(uint32_t base, int row0, int k0, int lane) {
    const int g = lane >> 3;
    const int row = row0 + (lane & 7) + ((g & 1) << 3);
    const int col = k0 + ((g >> 1) << 3);
    return base + (uint32_t)(row * STRD + col) * 2;
}

__device__ __forceinline__ void mma16816(float (&d)[4], const uint32_t (&a)[4],
                                         uint32_t b0, uint32_t b1) {
    asm volatile(
        "mma.sync.aligned.m16n8k16.row.col.f32.bf16.bf16.f32 "
        "{%0,%1,%2,%3},{%4,%5,%6,%7},{%8,%9},{%0,%1,%2,%3};"
        : "+f"(d[0]), "+f"(d[1]), "+f"(d[2]), "+f"(d[3])
        : "r"(a[0]), "r"(a[1]), "r"(a[2]), "r"(a[3]), "r"(b0), "r"(b1));
}

__device__ __forceinline__ void split8(const float* v, uint4& hi, uint4& lo) {
    unsigned short h[8], l[8];
    #pragma unroll
    for (int i = 0; i < 8; i++) {
        __nv_bfloat16 hb = __float2bfloat16_rn(v[i]);
        __nv_bfloat16 lb = __float2bfloat16_rn(v[i] - __bfloat162float(hb));
        h[i] = __bfloat16_as_ushort(hb);
        l[i] = __bfloat16_as_ushort(lb);
    }
    hi.x = h[0] | ((uint32_t)h[1] << 16); hi.y = h[2] | ((uint32_t)h[3] << 16);
    hi.z = h[4] | ((uint32_t)h[5] << 16); hi.w = h[6] | ((uint32_t)h[7] << 16);
    lo.x = l[0] | ((uint32_t)l[1] << 16); lo.y = l[2] | ((uint32_t)l[3] << 16);
    lo.z = l[4] | ((uint32_t)l[5] << 16); lo.w = l[6] | ((uint32_t)l[7] << 16);
}

// ---------------------------------------------------------------------------
// Projection: D = alpha*(X @ W^T + bias). M=8192, N=1024, K=1024, bf16x3 HMMA.
// CTA 128x128, K-chunk 32, 8 warps (2m x 4n), warp tile 64x32.
// split=1 -> bf16 hi/lo [z][l][d]; split=0 -> fp32 [z][l][d].
// ---------------------------------------------------------------------------
__global__ __launch_bounds__(256) void proj_mma(
    const float* __restrict__ X, const float* __restrict__ W,
    const float* __restrict__ bias, float alpha, int split,
    float* __restrict__ dstF,
    __nv_bfloat16* __restrict__ dstHi, __nv_bfloat16* __restrict__ dstLo)
{
    __shared__ __align__(16) unsigned short Ah[128 * STRD], Al[128 * STRD];
    __shared__ __align__(16) unsigned short Bh[128 * STRD], Bl[128 * STRD];
    const int t = threadIdx.x, lane = t & 31, wid = t >> 5;
    const int wm = wid >> 2, wn = wid & 3;
    const int bm = blockIdx.y * 128, bn = blockIdx.x * 128;
    const uint32_t ah = smem_u32(Ah), al = smem_u32(Al);
    const uint32_t bh = smem_u32(Bh), bl = smem_u32(Bl);

    const int row = t >> 1, cg = (t & 1) * 16;

    float acc[4][4][4];
    #pragma unroll
    for (int i = 0; i < 4; i++)
        #pragma unroll
        for (int j = 0; j < 4; j++)
            #pragma unroll
            for (int q = 0; q < 4; q++) acc[i][j][q] = 0.f;

    for (int kt = 0; kt < IND; kt += 32) {
        // load + split X, W chunk
        {
            const float* xp = X + (size_t)(bm + row) * IND + kt + cg;
            const float* wp = W + (size_t)(bn + row) * IND + kt + cg;
            float v[8]; uint4 hi, lo;
            #pragma unroll
            for (int s = 0; s < 2; s++) {
                *(float4*)v       = *(const float4*)(xp + s * 8);
                *(float4*)(v + 4) = *(const float4*)(xp + s * 8 + 4);
                split8(v, hi, lo);
                *(uint4*)&Ah[row * STRD + cg + s * 8] = hi;
                *(uint4*)&Al[row * STRD + cg + s * 8] = lo;
            }
            #pragma unroll
            for (int s = 0; s < 2; s++) {
                *(float4*)v       = *(const float4*)(wp + s * 8);
                *(float4*)(v + 4) = *(const float4*)(wp + s * 8 + 4);
                split8(v, hi, lo);
                *(uint4*)&Bh[row * STRD + cg + s * 8] = hi;
                *(uint4*)&Bl[row * STRD + cg + s * 8] = lo;
            }
        }
        __syncthreads();
        #pragma unroll
        for (int ks = 0; ks < 32; ks += 16) {
            uint32_t afh[4][4], afl[4][4], bfh[2][4], bfl[2][4];
            #pragma unroll
            for (int mi = 0; mi < 4; mi++) {
                ldsm4(afh[mi], frag_addr(ah, wm * 64 + mi * 16, ks, lane));
                ldsm4(afl[mi], frag_addr(al, wm * 64 + mi * 16, ks, lane));
            }
            #pragma unroll
            for (int ng = 0; ng < 2; ng++) {
                ldsm4(bfh[ng], frag_addr(bh, wn * 32 + ng * 16, ks, lane));
                ldsm4(bfl[ng], frag_addr(bl, wn * 32 + ng * 16, ks, lane));
            }
            #pragma unroll
            for (int mi = 0; mi < 4; mi++)
                #pragma unroll
                for (int nj = 0; nj < 4; nj++) {
                    const int ng = nj >> 1, hh = nj & 1;
                    mma16816(acc[mi][nj], afh[mi], bfh[ng][hh], bfh[ng][hh + 2]);
                    mma16816(acc[mi][nj], afh[mi], bfl[ng][hh], bfl[ng][hh + 2]);
                    mma16816(acc[mi][nj], afl[mi], bfh[ng][hh], bfh[ng][hh + 2]);
                }
        }
        __syncthreads();
    }

    // epilogue
    #pragma unroll
    for (int mi = 0; mi < 4; mi++)
        #pragma unroll
        for (int nj = 0; nj < 4; nj++) {
            const int r0 = bm + wm * 64 + mi * 16 + (lane >> 2);
            const int c  = bn + wn * 32 + nj * 8 + (lane & 3) * 2;
            const float b0 = bias[c], b1 = bias[c + 1];
            #pragma unroll
            for (int half = 0; half < 2; half++) {
                const int r = r0 + half * 8;
                const float v0 = alpha * (acc[mi][nj][half * 2]     + b0);
                const float v1 = alpha * (acc[mi][nj][half * 2 + 1] + b1);
                const size_t idx = (((size_t)(r >> 11) * NH_ + (c >> 6)) * 2048
                                    + (r & 2047)) * 64 + (c & 63);
                if (split) {
                    __nv_bfloat16 h0 = __float2bfloat16_rn(v0);
                    __nv_bfloat16 h1 = __float2bfloat16_rn(v1);
                    __nv_bfloat16 l0 = __float2bfloat16_rn(v0 - __bfloat162float(h0));
                    __nv_bfloat16 l1 = __float2bfloat16_rn(v1 - __bfloat162float(h1));
                    *(uint32_t*)&dstHi[idx] =
                        (uint32_t)__bfloat16_as_ushort(h0) |
                        ((uint32_t)__bfloat16_as_ushort(h1) << 16);
                    *(uint32_t*)&dstLo[idx] =
                        (uint32_t)__bfloat16_as_ushort(l0) |
                        ((uint32_t)__bfloat16_as_ushort(l1) << 16);
                } else {
                    *(float2*)&dstF[idx] = make_float2(v0, v1);
                }
            }
        }
}

// ---------------------------------------------------------------------------
// V transpose: g_Vf [z][l][64] fp32 -> g_Vt{hi,lo} [z][64][l] bf16.
// ---------------------------------------------------------------------------
__global__ __launch_bounds__(256) void vtrans_kernel()
{
    const int z = blockIdx.y, l0 = blockIdx.x * 64;
    __shared__ float tile[64][65];
    const int t = threadIdx.x, row = t >> 2, q = t & 3;
    #pragma unroll
    for (int i = 0; i < 4; i++) {
        float4 v = *(const float4*)&g_Vf[((size_t)z * 2048 + l0 + row) * 64 + q * 16 + i * 4];
        tile[row][q * 16 + i * 4 + 0] = v.x;
        tile[row][q * 16 + i * 4 + 1] = v.y;
        tile[row][q * 16 + i * 4 + 2] = v.z;
        tile[row][q * 16 + i * 4 + 3] = v.w;
    }
    __syncthreads();
    float v[16];
    #pragma unroll
    for (int i = 0; i < 16; i++) v[i] = tile[q * 16 + i][row];
    uint4 h0, l0v, h1, l1;
    split8(v, h0, l0v); split8(v + 8, h1, l1);
    const size_t base = ((size_t)z * 64 + row) * 2048 + l0 + q * 16;
    *(uint4*)&g_Vthi[base]     = h0;  *(uint4*)&g_Vthi[base + 8] = h1;
    *(uint4*)&g_Vtlo[base]     = l0v; *(uint4*)&g_Vtlo[base + 8] = l1;
}

// ---------------------------------------------------------------------------
// QK^T: 128x128 tile per CTA, K=64 (2 chunks of 32), bf16x3 HMMA.
// Epilogue: mask -> NEGV, write raw logits, per-(row, warp-32col) partials.
// ---------------------------------------------------------------------------
__global__ __launch_bounds__(256) void qk_mma(
    const int* __restrict__ mask, float* __restrict__ S)
{
    __shared__ __align__(16) unsigned short Qh[128 * STRD], Ql[128 * STRD];
    __shared__ __align__(16) unsigned short Kh[128 * STRD], Kl[128 * STRD];
    const int t = threadIdx.x, lane = t & 31, wid = t >> 5;
    const int wm = wid >> 2, wn = wid & 3;
    const int z = blockIdx.z, bm = blockIdx.y * 128, bn = blockIdx.x * 128;
    const uint32_t qh = smem_u32(Qh), ql = smem_u32(Ql);
    const uint32_t kh = smem_u32(Kh), kl = smem_u32(Kl);

    const int row = t >> 1, cg = (t & 1) * 16;

    float acc[4][4][4];
    #pragma unroll
    for (int i = 0; i < 4; i++)
        #pragma unroll
        for (int j = 0; j < 4; j++)
            #pragma unroll
            for (int q = 0; q < 4; q++) acc[i][j][q] = 0.f;

    for (int kt = 0; kt < 64; kt += 32) {
        const size_t qa = ((size_t)z * 2048 + bm + row) * 64 + kt + cg;
        const size_t ka = ((size_t)z * 2048 + bn + row) * 64 + kt + cg;
        #pragma unroll
        for (int s = 0; s < 2; s++) {
            *(uint4*)&Qh[row * STRD + cg + s * 8] = *(const uint4*)&g_Qhi[qa + s * 8];
            *(uint4*)&Ql[row * STRD + cg + s * 8] = *(const uint4*)&g_Qlo[qa + s * 8];
            *(uint4*)&Kh[row * STRD + cg + s * 8] = *(const uint4*)&g_Khi[ka + s * 8];
            *(uint4*)&Kl[row * STRD + cg + s * 8] = *(const uint4*)&g_Klo[ka + s * 8];
        }
        __syncthreads();
        #pragma unroll
        for (int ks = 0; ks < 32; ks += 16) {
            uint32_t afh[4][4], afl[4][4], bfh[2][4], bfl[2][4];
            #pragma unroll
            for (int mi = 0; mi < 4; mi++) {
                ldsm4(afh[mi], frag_addr(qh, wm * 64 + mi * 16, ks, lane));
                ldsm4(afl[mi], frag_addr(ql, wm * 64 + mi * 16, ks, lane));
            }
            #pragma unroll
            for (int ng = 0; ng < 2; ng++) {
                ldsm4(bfh[ng], frag_addr(kh, wn * 32 + ng * 16, ks, lane));
                ldsm4(bfl[ng], frag_addr(kl, wn * 32 + ng * 16, ks, lane));
            }
            #pragma unroll
            for (int mi = 0; mi < 4; mi++)
                #pragma unroll
                for (int nj = 0; nj < 4; nj++) {
                    const int ng = nj >> 1, hh = nj & 1;
                    mma16816(acc[mi][nj], afh[mi], bfh[ng][hh], bfh[ng][hh + 2]);
                    mma16816(acc[mi][nj], afh[mi], bfl[ng][hh], bfl[ng][hh + 2]);
                    mma16816(acc[mi][nj], afl[mi], bfh[ng][hh], bfh[ng][hh + 2]);
                }
        }
        __syncthreads();
    }

    // epilogue: mask + store + partial stats (per row instance: 8 vals/thread)
    float* Sz = S + (size_t)z * LQ_ * LK_;
    float2* part = g_part + ((size_t)z * 64 + blockIdx.x * 4 + wn) * LQ_;
    #pragma unroll
    for (int mi = 0; mi < 4; mi++)
        #pragma unroll
        for (int half = 0; half < 2; half++) {
            const int r = bm + wm * 64 + mi * 16 + (lane >> 2) + half * 8;
            float v[8];
            #pragma unroll
            for (int nj = 0; nj < 4; nj++) {
                const int c = bn + wn * 32 + nj * 8 + (lane & 3) * 2;
                const int2 mm = *(const int2*)&mask[(size_t)r * LK_ + c];
                v[nj * 2]     = mm.x ? acc[mi][nj][half * 2]     : NEGV;
                v[nj * 2 + 1] = mm.y ? acc[mi][nj][half * 2 + 1] : NEGV;
                *(float2*)&Sz[(size_t)r * LK_ + c] = make_float2(v[nj * 2], v[nj * 2 + 1]);
            }
            float mx = v[0];
            #pragma unroll
            for (int j = 1; j < 8; j++) mx = fmaxf(mx, v[j]);
            mx = fmaxf(mx, __shfl_xor_sync(0xffffffffu, mx, 1));
            mx = fmaxf(mx, __shfl_xor_sync(0xffffffffu, mx, 2));
            float sm = 0.f;
            #pragma unroll
            for (int j = 0; j < 8; j++) sm += __expf(v[j] - mx);
            sm += __shfl_xor_sync(0xffffffffu, sm, 1);
            sm += __shfl_xor_sync(0xffffffffu, sm, 2);
            if ((lane & 3) == 0) part[r] = make_float2(mx, sm);
        }
}

// ---------------------------------------------------------------------------
// Combine 64 partial stats per row -> {rowmax, 1/rowsum}.
// ---------------------------------------------------------------------------
__global__ __launch_bounds__(256) void combine_kernel()
{
    const int idx = blockIdx.x * 256 + threadIdx.x;
    if (idx >= NZ * LQ_) return;
    const int z = idx >> 11, m = idx & 2047;
    const float2* p = g_part + (size_t)z * 64 * LQ_ + m;
    float M = -3.4e38f;
    #pragma unroll 8
    for (int i = 0; i < 64; i++) M = fmaxf(M, p[(size_t)i * LQ_].x);
    float Ssum = 0.f;
    #pragma unroll 8
    for (int i = 0; i < 64; i++) {
        const float2 q = p[(size_t)i * LQ_];
        Ssum += q.y * __expf(q.x - M);
    }
    g_stats[idx] = make_float2(M, 1.0f / Ssum);
}

// ---------------------------------------------------------------------------
// PV: normalize S (write final probs back), O = P @ Vt^T via bf16x3 HMMA.
// CTA: 128 q-rows x 64 d-cols, K-loop 2048 tokens in 32-chunks.
// 8 warps (4m x 2n), warp tile 32x32.
// ---------------------------------------------------------------------------
__global__ __launch_bounds__(256) void pv_mma(float* __restrict__ S)
{
    __shared__ __align__(16) unsigned short Ph[128 * STRD], Pl[128 * STRD];
    __shared__ __align__(16) unsigned short Vh[64 * STRD], Vl[64 * STRD];
    const int t = threadIdx.x, lane = t & 31, wid = t >> 5;
    const int wm = wid >> 1, wn = wid & 1;
    const int z = blockIdx.y, bm = blockIdx.x * 128;
    const uint32_t ph = smem_u32(Ph), pl = smem_u32(Pl);
    const uint32_t vh = smem_u32(Vh), vl = smem_u32(Vl);

    const int row = t >> 1, cg = (t & 1) * 16;
    const float2 st = g_stats[(size_t)z * LQ_ + bm + row];
    float* Sr = S + (size_t)z * LQ_ * LK_ + (size_t)(bm + row) * LK_;

    const int vrow = row & 63;   // for t<128: rows 0..63

    float acc[2][4][4];
    #pragma unroll
    for (int i = 0; i < 2; i++)
        #pragma unroll
        for (int j = 0; j < 4; j++)
            #pragma unroll
            for (int q = 0; q < 4; q++) acc[i][j][q] = 0.f;

    for (int kt = 0; kt < LK_; kt += 32) {
        // normalize S chunk, split to Ph/Pl, write back
        {
            float v[8]; uint4 hi, lo;
            #pragma unroll
            for (int s = 0; s < 2; s++) {
                float* sp = Sr + kt + cg + s * 8;
                *(float4*)v       = *(const float4*)(sp);
                *(float4*)(v + 4) = *(const float4*)(sp + 4);
                #pragma unroll
                for (int j = 0; j < 8; j++) v[j] = __expf(v[j] - st.x) * st.y;
                *(float4*)(sp)     = make_float4(v[0], v[1], v[2], v[3]);
                *(float4*)(sp + 4) = make_float4(v[4], v[5], v[6], v[7]);
                split8(v, hi, lo);
                *(uint4*)&Ph[row * STRD + cg + s * 8] = hi;
                *(uint4*)&Pl[row * STRD + cg + s * 8] = lo;
            }
        }
        // V chunk: [64][32] hi/lo (first 128 threads)
        if (t < 128) {
            const size_t va = ((size_t)z * 64 + vrow) * 2048 + kt + cg;
            #pragma unroll
            for (int s = 0; s < 2; s++) {
                *(uint4*)&Vh[vrow * STRD + cg + s * 8] = *(const uint4*)&g_Vthi[va + s * 8];
                *(uint4*)&Vl[vrow * STRD + cg + s * 8] = *(const uint4*)&g_Vtlo[va + s * 8];
            }
        }
        __syncthreads();
        #pragma unroll
        for (int ks = 0; ks < 32; ks += 16) {
            uint32_t afh[2][4], afl[2][4], bfh[2][4], bfl[2][4];
            #pragma unroll
            for (int mi = 0; mi < 2; mi++) {
                ldsm4(afh[mi], frag_addr(ph, wm * 32 + mi * 16, ks, lane));
                ldsm4(afl[mi], frag_addr(pl, wm * 32 + mi * 16, ks, lane));
            }
            #pragma unroll
            for (int ng = 0; ng < 2; ng++) {
                ldsm4(bfh[ng], frag_addr(vh, wn * 32 + ng * 16, ks, lane));
                ldsm4(bfl[ng], frag_addr(vl, wn * 32 + ng * 16, ks, lane));
            }
            #pragma unroll
            for (int mi = 0; mi < 2; mi++)
                #pragma unroll
                for (int nj = 0; nj < 4; nj++) {
                    const int ng = nj >> 1, hh = nj & 1;
                    mma16816(acc[mi][nj], afh[mi], bfh[ng][hh], bfh[ng][hh + 2]);
                    mma16816(acc[mi][nj], afh[mi], bfl[ng][hh], bfl[ng][hh + 2]);
                    mma16816(acc[mi][nj], afl[mi], bfh[ng][hh], bfh[ng][hh + 2]);
                }
        }
        __syncthreads();
    }

    const int bb = z >> 4, h = z & 15;
    #pragma unroll
    for (int mi = 0; mi < 2; mi++)
        #pragma unroll
        for (int nj = 0; nj < 4; nj++) {
            const int r0 = bm + wm * 32 + mi * 16 + (lane >> 2);
            const int c  = wn * 32 + nj * 8 + (lane & 3) * 2;
            #pragma unroll
            for (int half = 0; half < 2; half++) {
                const int r = r0 + half * 8;
                *(float2*)&g_Oh[((size_t)bb * LQ_ + r) * HDA + h * 64 + c] =
                    make_float2(acc[mi][nj][half * 2], acc[mi][nj][half * 2 + 1]);
            }
        }
}

// ---------------------------------------------------------------------------
// Output GEMM (SIMT): out = Oh @ wo^T + bo.  M=8192, N=64, K=1024.
// ---------------------------------------------------------------------------
__global__ __launch_bounds__(256) void o_kernel(
    const float* __restrict__ wo, const float* __restrict__ bo,
    float* __restrict__ out)
{
    const int bm = blockIdx.x * 64;
    __shared__ float As[16][68];
    __shared__ float Ws[16][68];
    const int t = threadIdx.x;
    const int tx = t % 16, ty = t / 16;
    const int lk = t % 16, lr = t / 16;

    float acc[4][4];
    #pragma unroll
    for (int i = 0; i < 4; i++)
        #pragma unroll
        for (int j = 0; j < 4; j++) acc[i][j] = 0.f;

    for (int kt = 0; kt < HDA; kt += 16) {
        #pragma unroll
        for (int i = 0; i < 4; i++) {
            const int m = i * 16 + lr;
            As[lk][m] = g_Oh[(size_t)(bm + m) * HDA + kt + lk];
            Ws[lk][m] = wo  [(size_t)m        * HDA + kt + lk];
        }
        __syncthreads();
        #pragma unroll
        for (int kk = 0; kk < 16; kk++) {
            float a[4], b[4];
            #pragma unroll
            for (int i = 0; i < 4; i++) a[i] = As[kk][ty * 4 + i];
            #pragma unroll
            for (int j = 0; j < 4; j++) b[j] = Ws[kk][tx + 16 * j];
            #pragma unroll
            for (int i = 0; i < 4; i++)
                #pragma unroll
                for (int j = 0; j < 4; j++) acc[i][j] += a[i] * b[j];
        }
        __syncthreads();
    }

    #pragma unroll
    for (int i = 0; i < 4; i++) {
        const int m = bm + ty * 4 + i;
        #pragma unroll
        for (int j = 0; j < 4; j++) {
            const int n = tx + 16 * j;
            out[(size_t)m * HD_ + n] = acc[i][j] + bo[n];
        }
    }
}

// ---------------------------------------------------------------------------
extern "C" void kernel_launch(void* const* d_in, const int* in_sizes, int n_in,
                              void* d_out, int out_size)
{
    (void)in_sizes; (void)n_in; (void)out_size;
    const float* q    = (const float*)d_in[0];
    const float* k    = (const float*)d_in[1];
    const float* v    = (const float*)d_in[2];
    const int*   mask = (const int*)  d_in[3];
    const float* wq   = (const float*)d_in[4];
    const float* bq   = (const float*)d_in[5];
    const float* wk   = (const float*)d_in[6];
    const float* bk   = (const float*)d_in[7];
    const float* wv   = (const float*)d_in[8];
    const float* bv   = (const float*)d_in[9];
    const float* wo   = (const float*)d_in[10];
    const float* bo   = (const float*)d_in[11];

    float* out    = (float*)d_out;
    float* scores = out + (size_t)B_ * LQ_ * HD_;

    __nv_bfloat16 *Qhi, *Qlo, *Khi, *Klo;
    float* Vf;
    cudaGetSymbolAddress((void**)&Qhi, g_Qhi);
    cudaGetSymbolAddress((void**)&Qlo, g_Qlo);
    cudaGetSymbolAddress((void**)&Khi, g_Khi);
    cudaGetSymbolAddress((void**)&Klo, g_Klo);
    cudaGetSymbolAddress((void**)&Vf,  g_Vf);

    const dim3 blk(256);
    const dim3 gproj(IND / 128, (B_ * LQ_) / 128);   // (8, 64)
    proj_mma<<<gproj, blk>>>(q, wq, bq, 0.125f, 1, nullptr, Qhi, Qlo);
    proj_mma<<<gproj, blk>>>(k, wk, bk, 1.0f,   1, nullptr, Khi, Klo);
    proj_mma<<<gproj, blk>>>(v, wv, bv, 1.0f,   0, Vf, nullptr, nullptr);

    vtrans_kernel<<<dim3(LK_ / 64, NZ), blk>>>();    // (32, 64)

    qk_mma<<<dim3(LK_ / 128, LQ_ / 128, NZ), blk>>>(mask, scores);

    combine_kernel<<<(NZ * LQ_ + 255) / 256, blk>>>();

    pv_mma<<<dim3(LQ_ / 128, NZ), blk>>>(scores);

    o_kernel<<<(B_ * LQ_) / 64, blk>>>(wo, bo, out);
}

// round 7
// speedup vs baseline: 1.7530x; 1.7530x over previous
#include <cuda_runtime.h>
#include <math.h>
#include <cstdint>

#define B_   4
#define LQ_  2048
#define LK_  2048
#define IND  1024
#define NH_  16
#define HD_  64
#define HDA  1024
#define NZ   (B_*NH_)
#define NEGV (-1e9f)

// Scratch (device globals — no allocation allowed)
__device__ float  g_Qh[(size_t)NZ * HD_ * LQ_];   // [z][d][q]  (transposed, pre-scaled)
__device__ float  g_Kh[(size_t)NZ * HD_ * LK_];   // [z][d][k]  (transposed)
__device__ float  g_Vh[(size_t)NZ * LK_ * HD_];   // [z][k][d]
__device__ float  g_Oh[(size_t)B_ * LQ_ * HDA];   // [b][q][h*d]
__device__ float2 g_part[(size_t)NZ * 16 * LQ_];  // per-(z, n-tile, row) {max, expsum}
__device__ float2 g_stats[(size_t)NZ * LQ_];      // {rowmax, 1/rowsum}

// ---------------- packed f32x2 helpers (sm_100+ base ISA) ----------------
__device__ __forceinline__ unsigned long long pack2(float x, float y) {
    unsigned long long r;
    asm("mov.b64 %0, {%1, %2};" : "=l"(r) : "f"(x), "f"(y));
    return r;
}
__device__ __forceinline__ float2 unpack2(unsigned long long v) {
    float x, y;
    asm("mov.b64 {%0, %1}, %2;" : "=f"(x), "=f"(y) : "l"(v));
    return make_float2(x, y);
}
__device__ __forceinline__ unsigned long long ffma2(
    unsigned long long a, unsigned long long b, unsigned long long c) {
    unsigned long long d;
    asm("fma.rn.f32x2 %0, %1, %2, %3;" : "=l"(d) : "l"(a), "l"(b), "l"(c));
    return d;
}

// ---------------------------------------------------------------------------
// Projection GEMM: Y = alpha*(X @ W^T + bias). 128x128x16 tile, 256 threads,
// 8x8 microtile via f32x2. transposed=1 -> Y[z][d][l], else Y[z][l][d].
// ---------------------------------------------------------------------------
__global__ __launch_bounds__(256) void proj_kernel(
    const float* __restrict__ X, const float* __restrict__ W,
    const float* __restrict__ bias, float* __restrict__ Y,
    float alpha, int transposed)
{
    const int bm = blockIdx.y * 128;
    const int bn = blockIdx.x * 128;
    __shared__ float As[16][132];
    __shared__ float Bs[16][132];
    const int t  = threadIdx.x;
    const int tx = t & 15, ty = t >> 4;
    const int r  = t >> 1, half = t & 1;

    const float* Ap = X + (size_t)(bm + r) * IND + half * 8;
    const float* Bp = W + (size_t)(bn + r) * IND + half * 8;

    float4 a0 = *(const float4*)(Ap);
    float4 a1 = *(const float4*)(Ap + 4);
    float4 b0 = *(const float4*)(Bp);
    float4 b1 = *(const float4*)(Bp + 4);

    unsigned long long acc2[8][4];
    #pragma unroll
    for (int i = 0; i < 8; i++)
        #pragma unroll
        for (int j = 0; j < 4; j++) acc2[i][j] = pack2(0.f, 0.f);

    for (int kt = 0; kt < IND; kt += 16) {
        const int c = half * 8;
        As[c+0][r]=a0.x; As[c+1][r]=a0.y; As[c+2][r]=a0.z; As[c+3][r]=a0.w;
        As[c+4][r]=a1.x; As[c+5][r]=a1.y; As[c+6][r]=a1.z; As[c+7][r]=a1.w;
        Bs[c+0][r]=b0.x; Bs[c+1][r]=b0.y; Bs[c+2][r]=b0.z; Bs[c+3][r]=b0.w;
        Bs[c+4][r]=b1.x; Bs[c+5][r]=b1.y; Bs[c+6][r]=b1.z; Bs[c+7][r]=b1.w;
        __syncthreads();
        if (kt + 16 < IND) {
            a0 = *(const float4*)(Ap + kt + 16);
            a1 = *(const float4*)(Ap + kt + 20);
            b0 = *(const float4*)(Bp + kt + 16);
            b1 = *(const float4*)(Bp + kt + 20);
        }
        #pragma unroll
        for (int kk = 0; kk < 16; kk++) {
            float4 x0 = *(const float4*)&As[kk][ty * 8];
            float4 x1 = *(const float4*)&As[kk][ty * 8 + 4];
            float4 y0 = *(const float4*)&Bs[kk][tx * 8];
            float4 y1 = *(const float4*)&Bs[kk][tx * 8 + 4];
            unsigned long long bb2[4] = {
                pack2(y0.x, y0.y), pack2(y0.z, y0.w),
                pack2(y1.x, y1.y), pack2(y1.z, y1.w)};
            float a[8] = {x0.x,x0.y,x0.z,x0.w,x1.x,x1.y,x1.z,x1.w};
            #pragma unroll
            for (int i = 0; i < 8; i++) {
                const unsigned long long a2 = pack2(a[i], a[i]);
                #pragma unroll
                for (int j = 0; j < 4; j++)
                    acc2[i][j] = ffma2(a2, bb2[j], acc2[i][j]);
            }
        }
        __syncthreads();
    }

    if (!transposed) {
        #pragma unroll
        for (int i = 0; i < 8; i++) {
            const int m  = bm + ty * 8 + i;
            const int bb = m >> 11, l = m & 2047;
            const int n0 = bn + tx * 8;
            const int h  = n0 >> 6, dd = n0 & 63;
            float* dst = Y + (((size_t)(bb * NH_ + h) * LK_) + l) * HD_ + dd;
            float2 p0 = unpack2(acc2[i][0]), p1 = unpack2(acc2[i][1]);
            float2 p2 = unpack2(acc2[i][2]), p3 = unpack2(acc2[i][3]);
            float4 o0, o1;
            o0.x = alpha * (p0.x + bias[n0+0]);
            o0.y = alpha * (p0.y + bias[n0+1]);
            o0.z = alpha * (p1.x + bias[n0+2]);
            o0.w = alpha * (p1.y + bias[n0+3]);
            o1.x = alpha * (p2.x + bias[n0+4]);
            o1.y = alpha * (p2.y + bias[n0+5]);
            o1.z = alpha * (p3.x + bias[n0+6]);
            o1.w = alpha * (p3.y + bias[n0+7]);
            *(float4*)(dst)     = o0;
            *(float4*)(dst + 4) = o1;
        }
    } else {
        const int m0 = bm + ty * 8;
        const int bb = m0 >> 11, l0 = m0 & 2047;
        float v[8][8];
        #pragma unroll
        for (int i = 0; i < 8; i++) {
            float2 p0 = unpack2(acc2[i][0]), p1 = unpack2(acc2[i][1]);
            float2 p2 = unpack2(acc2[i][2]), p3 = unpack2(acc2[i][3]);
            v[i][0]=p0.x; v[i][1]=p0.y; v[i][2]=p1.x; v[i][3]=p1.y;
            v[i][4]=p2.x; v[i][5]=p2.y; v[i][6]=p3.x; v[i][7]=p3.y;
        }
        #pragma unroll
        for (int j = 0; j < 8; j++) {
            const int n  = bn + tx * 8 + j;
            const int h  = n >> 6, dd = n & 63;
            float* dst = Y + (((size_t)(bb * NH_ + h) * HD_) + dd) * LQ_ + l0;
            float4 o0, o1;
            o0.x = alpha * (v[0][j] + bias[n]);
            o0.y = alpha * (v[1][j] + bias[n]);
            o0.z = alpha * (v[2][j] + bias[n]);
            o0.w = alpha * (v[3][j] + bias[n]);
            o1.x = alpha * (v[4][j] + bias[n]);
            o1.y = alpha * (v[5][j] + bias[n]);
            o1.z = alpha * (v[6][j] + bias[n]);
            o1.w = alpha * (v[7][j] + bias[n]);
            *(float4*)(dst)     = o0;
            *(float4*)(dst + 4) = o1;
        }
    }
}

// ---------------------------------------------------------------------------
// QK^T: S[m,n] = sum_d Qh[z][d][m]*Kh[z][d][n], masked; raw logits + partials.
// ---------------------------------------------------------------------------
__global__ __launch_bounds__(256) void qk_kernel(
    const int* __restrict__ mask, float* __restrict__ S)
{
    const int z  = blockIdx.z;
    const int bm = blockIdx.y * 128;
    const int bn = blockIdx.x * 128;
    const float* Q = g_Qh + (size_t)z * HD_ * LQ_;
    const float* K = g_Kh + (size_t)z * HD_ * LK_;

    __shared__ float As[16][132];
    __shared__ float Bs[16][132];
    const int t  = threadIdx.x;
    const int tx = t & 15, ty = t >> 4;
    const int dr = t >> 4, g = t & 15;

    unsigned long long acc2[8][4];
    #pragma unroll
    for (int i = 0; i < 8; i++)
        #pragma unroll
        for (int j = 0; j < 4; j++) acc2[i][j] = pack2(0.f, 0.f);

    for (int kt = 0; kt < HD_; kt += 16) {
        const float* qp = Q + (size_t)(kt + dr) * LQ_ + bm + g * 8;
        const float* kp = K + (size_t)(kt + dr) * LK_ + bn + g * 8;
        *(float4*)&As[dr][g * 8]     = *(const float4*)(qp);
        *(float4*)&As[dr][g * 8 + 4] = *(const float4*)(qp + 4);
        *(float4*)&Bs[dr][g * 8]     = *(const float4*)(kp);
        *(float4*)&Bs[dr][g * 8 + 4] = *(const float4*)(kp + 4);
        __syncthreads();
        #pragma unroll
        for (int kk = 0; kk < 16; kk++) {
            float4 x0 = *(const float4*)&As[kk][ty * 8];
            float4 x1 = *(const float4*)&As[kk][ty * 8 + 4];
            float4 y0 = *(const float4*)&Bs[kk][tx * 8];
            float4 y1 = *(const float4*)&Bs[kk][tx * 8 + 4];
            unsigned long long bb2[4] = {
                pack2(y0.x, y0.y), pack2(y0.z, y0.w),
                pack2(y1.x, y1.y), pack2(y1.z, y1.w)};
            float a[8] = {x0.x,x0.y,x0.z,x0.w,x1.x,x1.y,x1.z,x1.w};
            #pragma unroll
            for (int i = 0; i < 8; i++) {
                const unsigned long long a2 = pack2(a[i], a[i]);
                #pragma unroll
                for (int j = 0; j < 4; j++)
                    acc2[i][j] = ffma2(a2, bb2[j], acc2[i][j]);
            }
        }
        __syncthreads();
    }

    // Epilogue: mask, write raw logits, per-block-row partial stats
    float* Sz = S + (size_t)z * LQ_ * LK_;
    float2* part = g_part + ((size_t)z * 16 + blockIdx.x) * LQ_;
    #pragma unroll
    for (int i = 0; i < 8; i++) {
        const int m  = bm + ty * 8 + i;
        const int n0 = bn + tx * 8;
        float v[8];
        {
            float2 p0 = unpack2(acc2[i][0]), p1 = unpack2(acc2[i][1]);
            float2 p2 = unpack2(acc2[i][2]), p3 = unpack2(acc2[i][3]);
            v[0]=p0.x; v[1]=p0.y; v[2]=p1.x; v[3]=p1.y;
            v[4]=p2.x; v[5]=p2.y; v[6]=p3.x; v[7]=p3.y;
        }
        const int4 m0 = *(const int4*)&mask[(size_t)m * LK_ + n0];
        const int4 m1 = *(const int4*)&mask[(size_t)m * LK_ + n0 + 4];
        v[0] = m0.x ? v[0] : NEGV;
        v[1] = m0.y ? v[1] : NEGV;
        v[2] = m0.z ? v[2] : NEGV;
        v[3] = m0.w ? v[3] : NEGV;
        v[4] = m1.x ? v[4] : NEGV;
        v[5] = m1.y ? v[5] : NEGV;
        v[6] = m1.z ? v[6] : NEGV;
        v[7] = m1.w ? v[7] : NEGV;

        float mx = v[0];
        #pragma unroll
        for (int j = 1; j < 8; j++) mx = fmaxf(mx, v[j]);
        #pragma unroll
        for (int o = 8; o > 0; o >>= 1)
            mx = fmaxf(mx, __shfl_xor_sync(0xffffffffu, mx, o));
        float s = 0.f;
        #pragma unroll
        for (int j = 0; j < 8; j++) s += __expf(v[j] - mx);
        #pragma unroll
        for (int o = 8; o > 0; o >>= 1)
            s += __shfl_xor_sync(0xffffffffu, s, o);

        *(float4*)&Sz[(size_t)m * LK_ + n0]     = make_float4(v[0], v[1], v[2], v[3]);
        *(float4*)&Sz[(size_t)m * LK_ + n0 + 4] = make_float4(v[4], v[5], v[6], v[7]);
        if (tx == 0) part[m] = make_float2(mx, s);
    }
}

// ---------------------------------------------------------------------------
// Combine 16 partial stats per row -> {rowmax, 1/rowsum}.
// ---------------------------------------------------------------------------
__global__ __launch_bounds__(256) void combine_kernel()
{
    const int idx = blockIdx.x * 256 + threadIdx.x;
    if (idx >= NZ * LQ_) return;
    const int z = idx >> 11, m = idx & 2047;
    const float2* p = g_part + (size_t)z * 16 * LQ_ + m;
    float M = -3.4e38f;
    #pragma unroll
    for (int i = 0; i < 16; i++) M = fmaxf(M, p[(size_t)i * LQ_].x);
    float Ssum = 0.f;
    #pragma unroll
    for (int i = 0; i < 16; i++) {
        const float2 q = p[(size_t)i * LQ_];
        Ssum += q.y * __expf(q.x - M);
    }
    g_stats[idx] = make_float2(M, 1.0f / Ssum);
}

// ---------------------------------------------------------------------------
// PV fused with normalization. 128x64x16, 256 threads, 8x4 microtile, f32x2.
// ---------------------------------------------------------------------------
__global__ __launch_bounds__(256) void pv_kernel(float* __restrict__ S)
{
    const int z  = blockIdx.y;
    const int bm = blockIdx.x * 128;
    const float* V = g_Vh + (size_t)z * LK_ * HD_;
    float* Sz = S + (size_t)z * LQ_ * LK_;

    __shared__ float Ps[16][132];
    __shared__ float Vs[16][68];
    const int t  = threadIdx.x;
    const int tx = t & 15, ty = t >> 4;
    const int r  = t >> 1, half = t & 1;
    const int vk = t >> 4, vg = t & 15;

    const float2 st = g_stats[(size_t)z * LQ_ + bm + r];

    unsigned long long acc2[8][2];
    #pragma unroll
    for (int i = 0; i < 8; i++) {
        acc2[i][0] = pack2(0.f, 0.f);
        acc2[i][1] = pack2(0.f, 0.f);
    }

    for (int kt = 0; kt < LK_; kt += 16) {
        float* sp = &Sz[(size_t)(bm + r) * LK_ + kt + half * 8];
        float4 s0 = *(const float4*)(sp);
        float4 s1 = *(const float4*)(sp + 4);
        s0.x = __expf(s0.x - st.x) * st.y;
        s0.y = __expf(s0.y - st.x) * st.y;
        s0.z = __expf(s0.z - st.x) * st.y;
        s0.w = __expf(s0.w - st.x) * st.y;
        s1.x = __expf(s1.x - st.x) * st.y;
        s1.y = __expf(s1.y - st.x) * st.y;
        s1.z = __expf(s1.z - st.x) * st.y;
        s1.w = __expf(s1.w - st.x) * st.y;
        *(float4*)(sp)     = s0;             // final normalized scores
        *(float4*)(sp + 4) = s1;
        const int c = half * 8;
        Ps[c+0][r]=s0.x; Ps[c+1][r]=s0.y; Ps[c+2][r]=s0.z; Ps[c+3][r]=s0.w;
        Ps[c+4][r]=s1.x; Ps[c+5][r]=s1.y; Ps[c+6][r]=s1.z; Ps[c+7][r]=s1.w;

        *(float4*)&Vs[vk][vg * 4] = *(const float4*)&V[(size_t)(kt + vk) * HD_ + vg * 4];
        __syncthreads();
        #pragma unroll
        for (int kk = 0; kk < 16; kk++) {
            float4 x0 = *(const float4*)&Ps[kk][ty * 8];
            float4 x1 = *(const float4*)&Ps[kk][ty * 8 + 4];
            float4 b4 = *(const float4*)&Vs[kk][tx * 4];
            unsigned long long b20 = pack2(b4.x, b4.y);
            unsigned long long b21 = pack2(b4.z, b4.w);
            float a[8] = {x0.x,x0.y,x0.z,x0.w,x1.x,x1.y,x1.z,x1.w};
            #pragma unroll
            for (int i = 0; i < 8; i++) {
                const unsigned long long a2 = pack2(a[i], a[i]);
                acc2[i][0] = ffma2(a2, b20, acc2[i][0]);
                acc2[i][1] = ffma2(a2, b21, acc2[i][1]);
            }
        }
        __syncthreads();
    }

    const int bb = z >> 4, h = z & 15;
    #pragma unroll
    for (int i = 0; i < 8; i++) {
        const int q = bm + ty * 8 + i;
        float2 p0 = unpack2(acc2[i][0]), p1 = unpack2(acc2[i][1]);
        float4 o = {p0.x, p0.y, p1.x, p1.y};
        *(float4*)&g_Oh[((size_t)bb * LQ_ + q) * HDA + h * HD_ + tx * 4] = o;
    }
}

// ---------------------------------------------------------------------------
// Output GEMM: out = Oh @ wo^T + bo, M=8192, N=64, K=1024. f32x2.
// ---------------------------------------------------------------------------
__global__ __launch_bounds__(256) void o_kernel(
    const float* __restrict__ wo, const float* __restrict__ bo,
    float* __restrict__ out)
{
    const int bm = blockIdx.x * 64;
    __shared__ float As[16][68];
    __shared__ float Ws[16][68];
    const int t  = threadIdx.x;
    const int tx = t % 16, ty = t / 16;
    const int lk = t % 16, lr = t / 16;

    unsigned long long acc2[4][2];
    #pragma unroll
    for (int i = 0; i < 4; i++) {
        acc2[i][0] = pack2(0.f, 0.f);
        acc2[i][1] = pack2(0.f, 0.f);
    }

    for (int kt = 0; kt < HDA; kt += 16) {
        #pragma unroll
        for (int i = 0; i < 4; i++) {
            const int m = i * 16 + lr;
            As[lk][m] = g_Oh[(size_t)(bm + m) * HDA + kt + lk];
            Ws[lk][m] = wo  [(size_t)m        * HDA + kt + lk];
        }
        __syncthreads();
        #pragma unroll
        for (int kk = 0; kk < 16; kk++) {
            float a[4], b[4];
            #pragma unroll
            for (int i = 0; i < 4; i++) a[i] = As[kk][ty * 4 + i];
            #pragma unroll
            for (int j = 0; j < 4; j++) b[j] = Ws[kk][tx + 16 * j];
            const unsigned long long b20 = pack2(b[0], b[1]);
            const unsigned long long b21 = pack2(b[2], b[3]);
            #pragma unroll
            for (int i = 0; i < 4; i++) {
                const unsigned long long a2 = pack2(a[i], a[i]);
                acc2[i][0] = ffma2(a2, b20, acc2[i][0]);
                acc2[i][1] = ffma2(a2, b21, acc2[i][1]);
            }
        }
        __syncthreads();
    }

    #pragma unroll
    for (int i = 0; i < 4; i++) {
        const int m = bm + ty * 4 + i;
        float2 p0 = unpack2(acc2[i][0]), p1 = unpack2(acc2[i][1]);
        out[(size_t)m * HD_ + tx]      = p0.x + bo[tx];
        out[(size_t)m * HD_ + tx + 16] = p0.y + bo[tx + 16];
        out[(size_t)m * HD_ + tx + 32] = p1.x + bo[tx + 32];
        out[(size_t)m * HD_ + tx + 48] = p1.y + bo[tx + 48];
    }
}

// ---------------------------------------------------------------------------
extern "C" void kernel_launch(void* const* d_in, const int* in_sizes, int n_in,
                              void* d_out, int out_size)
{
    (void)in_sizes; (void)n_in; (void)out_size;
    const float* q    = (const float*)d_in[0];
    const float* k    = (const float*)d_in[1];
    const float* v    = (const float*)d_in[2];
    const int*   mask = (const int*)  d_in[3];
    const float* wq   = (const float*)d_in[4];
    const float* bq   = (const float*)d_in[5];
    const float* wk   = (const float*)d_in[6];
    const float* bk   = (const float*)d_in[7];
    const float* wv   = (const float*)d_in[8];
    const float* bv   = (const float*)d_in[9];
    const float* wo   = (const float*)d_in[10];
    const float* bo   = (const float*)d_in[11];

    float* out    = (float*)d_out;                       // [B, LQ, 64]
    float* scores = out + (size_t)B_ * LQ_ * HD_;        // [B, H, LQ, LK]

    float *Qh, *Kh, *Vh;
    cudaGetSymbolAddress((void**)&Qh, g_Qh);
    cudaGetSymbolAddress((void**)&Kh, g_Kh);
    cudaGetSymbolAddress((void**)&Vh, g_Vh);

    const dim3 blk(256);
    const dim3 gproj(IND / 128, (B_ * LQ_) / 128);       // (8, 64)
    proj_kernel<<<gproj, blk>>>(q, wq, bq, Qh, 0.125f, 1);  // -> [z][d][q]
    proj_kernel<<<gproj, blk>>>(k, wk, bk, Kh, 1.0f,   1);  // -> [z][d][k]
    proj_kernel<<<gproj, blk>>>(v, wv, bv, Vh, 1.0f,   0);  // -> [z][k][d]

    const dim3 gqk(LK_ / 128, LQ_ / 128, NZ);            // (16,16,64)
    qk_kernel<<<gqk, blk>>>(mask, scores);

    combine_kernel<<<(NZ * LQ_ + 255) / 256, blk>>>();   // 512 blocks

    const dim3 gpv(LQ_ / 128, NZ);                       // (16,64)
    pv_kernel<<<gpv, blk>>>(scores);

    o_kernel<<<(B_ * LQ_) / 64, blk>>>(wo, bo, out);     // 128 blocks
}